// round 2
// baseline (speedup 1.0000x reference)
#include <cuda_runtime.h>
#include <math.h>
#include <stdint.h>

// Problem constants (fixed by dataset)
#define BQ    32        // batch (queries)
#define ZDIM  512       // input embed dim
#define HDIM  256       // hidden dim
#define NMAX  20032     // max docs rounded up to 64
#define TOPK  5

// ---------------- device scratch ----------------
__device__ __align__(16) float g_qa [BQ * HDIM];          // qa + b1
__device__ __align__(16) float g_dt [NMAX * HDIM];        // doc transform output
__device__ __align__(16) float g_da [NMAX * HDIM];        // d_t @ W1[H:]
__device__ __align__(16) float g_raw[BQ * NMAX];          // raw scores

// ---------------- helpers ----------------
__device__ __forceinline__ float gelu_exact(float x) {
    // exact gelu = x * Phi(x)
    return x * normcdff(x);
}

__device__ __forceinline__ float warp_sum(float v) {
    #pragma unroll
    for (int o = 16; o > 0; o >>= 1) v += __shfl_xor_sync(0xffffffffu, v, o);
    return v;
}

// ---------------- query path: q_t = LN(gelu(q@Wq+bq)); qa = q_t@W1[:H] + b1 ----------------
__global__ void kq_kernel(const float* __restrict__ q,
                          const float* __restrict__ Wq, const float* __restrict__ bq,
                          const float* __restrict__ lnw, const float* __restrict__ lnb,
                          const float* __restrict__ W1, const float* __restrict__ b1) {
    __shared__ float sq[ZDIM];
    __shared__ float st[HDIM];
    __shared__ float red[16];
    int b = blockIdx.x, tid = threadIdx.x;
    sq[tid]       = q[b * ZDIM + tid];
    sq[tid + 256] = q[b * ZDIM + 256 + tid];
    __syncthreads();

    float acc = bq[tid];
    #pragma unroll 8
    for (int kk = 0; kk < ZDIM; kk++) acc = fmaf(sq[kk], Wq[kk * HDIM + tid], acc);
    float g = gelu_exact(acc);

    int lane = tid & 31, w = tid >> 5;
    float s = warp_sum(g);
    if (lane == 0) red[w] = s;
    __syncthreads();
    float tot = 0.f;
    #pragma unroll
    for (int i = 0; i < 8; i++) tot += red[i];
    float mean = tot * (1.f / HDIM);

    float d = g - mean;
    float v = warp_sum(d * d);
    if (lane == 0) red[8 + w] = v;
    __syncthreads();
    float vt = 0.f;
    #pragma unroll
    for (int i = 0; i < 8; i++) vt += red[8 + i];
    float inv = rsqrtf(vt * (1.f / HDIM) + 1e-5f);

    float y = d * inv * lnw[tid] + lnb[tid];
    st[tid] = y;
    __syncthreads();

    float acc2 = b1[tid];
    #pragma unroll 8
    for (int h = 0; h < HDIM; h++) acc2 = fmaf(st[h], W1[h * HDIM + tid], acc2);
    g_qa[b * HDIM + tid] = acc2;
}

// ---------------- tiled GEMM: out[M,256] = A[M,K] @ B[K,256] (+bias, gelu, LN optional) ----------------
template <int K, bool ACT>
__global__ __launch_bounds__(256, 2)
void gemm_tile(const float* __restrict__ A, const float* __restrict__ B,
               const float* __restrict__ bias,
               const float* __restrict__ lnw, const float* __restrict__ lnb,
               float* __restrict__ out, int M) {
    __shared__ float  sA[64][32];
    __shared__ float4 sB[32][64];
    int tid = threadIdx.x, lane = tid & 31, w = tid >> 5;
    int r0 = blockIdx.x * 64;

    float acc[8][8];
    #pragma unroll
    for (int i = 0; i < 8; i++)
        #pragma unroll
        for (int j = 0; j < 8; j++) acc[i][j] = 0.f;

    for (int kc = 0; kc < K; kc += 32) {
        #pragma unroll
        for (int t = 0; t < 2; t++) {           // 512 float4 of A-chunk
            int f = tid + 256 * t, r = f >> 3, kg = f & 7;
            float4 vv = make_float4(0.f, 0.f, 0.f, 0.f);
            if (r0 + r < M) vv = *(const float4*)&A[(size_t)(r0 + r) * K + kc + kg * 4];
            *(float4*)&sA[r][kg * 4] = vv;
        }
        #pragma unroll
        for (int t = 0; t < 8; t++) {           // 2048 float4 of B-chunk
            int f = tid + 256 * t, kk = f >> 6, cg = f & 63;
            sB[kk][cg] = *(const float4*)&B[(size_t)(kc + kk) * HDIM + cg * 4];
        }
        __syncthreads();
        #pragma unroll 8
        for (int kk = 0; kk < 32; kk++) {
            float a_[8];
            #pragma unroll
            for (int i = 0; i < 8; i++) a_[i] = sA[w * 8 + i][kk];   // warp-uniform broadcast
            float4 b0 = sB[kk][lane * 2], b1v = sB[kk][lane * 2 + 1];
            float b_[8] = {b0.x, b0.y, b0.z, b0.w, b1v.x, b1v.y, b1v.z, b1v.w};
            #pragma unroll
            for (int i = 0; i < 8; i++)
                #pragma unroll
                for (int j = 0; j < 8; j++) acc[i][j] = fmaf(a_[i], b_[j], acc[i][j]);
        }
        __syncthreads();
    }

    int c0 = lane * 8;
    if (ACT) {
        float bb[8], lw[8], lb[8];
        #pragma unroll
        for (int j = 0; j < 8; j++) { bb[j] = bias[c0 + j]; lw[j] = lnw[c0 + j]; lb[j] = lnb[c0 + j]; }
        #pragma unroll
        for (int i = 0; i < 8; i++) {
            float g[8];
            #pragma unroll
            for (int j = 0; j < 8; j++) g[j] = gelu_exact(acc[i][j] + bb[j]);
            float s = 0.f;
            #pragma unroll
            for (int j = 0; j < 8; j++) s += g[j];
            s = warp_sum(s);
            float mean = s * (1.f / HDIM);
            float v = 0.f;
            #pragma unroll
            for (int j = 0; j < 8; j++) { float d = g[j] - mean; v += d * d; }
            v = warp_sum(v);
            float inv = rsqrtf(v * (1.f / HDIM) + 1e-5f);
            int row = r0 + w * 8 + i;
            if (row < M) {
                float o[8];
                #pragma unroll
                for (int j = 0; j < 8; j++) o[j] = (g[j] - mean) * inv * lw[j] + lb[j];
                float4* op = (float4*)&out[(size_t)row * HDIM + c0];
                op[0] = make_float4(o[0], o[1], o[2], o[3]);
                op[1] = make_float4(o[4], o[5], o[6], o[7]);
            }
        }
    } else {
        #pragma unroll
        for (int i = 0; i < 8; i++) {
            int row = r0 + w * 8 + i;
            if (row < M) {
                float4* op = (float4*)&out[(size_t)row * HDIM + c0];
                op[0] = make_float4(acc[i][0], acc[i][1], acc[i][2], acc[i][3]);
                op[1] = make_float4(acc[i][4], acc[i][5], acc[i][6], acc[i][7]);
            }
        }
    }
}

// ---------------- score kernel: raw[b,n] = b2 + sum_h W2[h]*gelu(qa[b,h]+da[n,h]) ----------------
__global__ __launch_bounds__(256)
void score_kernel(const float* __restrict__ W2, const float* __restrict__ b2, int N) {
    __shared__ float4 sqa[BQ * 64];   // qa as float4 [b][c/4], 32 KB
    int tid = threadIdx.x, lane = tid & 31, w = tid >> 5;
    #pragma unroll
    for (int t = 0; t < 8; t++) { int f = tid + 256 * t; sqa[f] = ((const float4*)g_qa)[f]; }
    float w2_[8];
    #pragma unroll
    for (int j = 0; j < 8; j++) w2_[j] = W2[lane * 8 + j];
    float b2v = b2[0];
    __syncthreads();

    int n0 = blockIdx.x * 16;
    for (int t = 0; t < 16; t++) {
        int n = n0 + t;
        if (n >= N) break;
        const float4* dap = (const float4*)&g_da[(size_t)n * HDIM + lane * 8];
        float4 d0 = dap[0], d1 = dap[1];
        float da_[8] = {d0.x, d0.y, d0.z, d0.w, d1.x, d1.y, d1.z, d1.w};
        #pragma unroll
        for (int bb = 0; bb < 4; bb++) {
            int b = w + bb * 8;
            float4 q0 = sqa[b * 64 + lane * 2], q1 = sqa[b * 64 + lane * 2 + 1];
            float qa_[8] = {q0.x, q0.y, q0.z, q0.w, q1.x, q1.y, q1.z, q1.w};
            float acc = 0.f;
            #pragma unroll
            for (int j = 0; j < 8; j++) acc = fmaf(w2_[j], gelu_exact(qa_[j] + da_[j]), acc);
            acc = warp_sum(acc);
            if (lane == 0) g_raw[(size_t)b * N + n] = acc + b2v;
        }
    }
}

// ---------------- top-k (k=5, lowest-index tie break) + softmax ----------------
__global__ __launch_bounds__(256)
void topk_kernel(const float* __restrict__ temp, float* __restrict__ out, int N) {
    __shared__ float ss[TOPK * 256];
    __shared__ int   si[TOPK * 256];
    int b = blockIdx.x, tid = threadIdx.x;
    float s[TOPK]; int id[TOPK];
    #pragma unroll
    for (int i = 0; i < TOPK; i++) { s[i] = -__int_as_float(0x7f800000); id[i] = 0x7fffffff; }

    const float* row = &g_raw[(size_t)b * N];
    for (int n = tid; n < N; n += 256) {
        float v = row[n];
        if (v > s[TOPK - 1]) {
            int p = TOPK - 1;
            #pragma unroll
            for (int i = TOPK - 1; i > 0; i--) if (v > s[i - 1]) p = i - 1;
            #pragma unroll
            for (int i = TOPK - 1; i > 0; i--) if (i > p) { s[i] = s[i - 1]; id[i] = id[i - 1]; }
            s[p] = v; id[p] = n;
        }
    }
    #pragma unroll
    for (int i = 0; i < TOPK; i++) { ss[i * 256 + tid] = s[i]; si[i * 256 + tid] = id[i]; }
    __syncthreads();

    for (int step = 128; step > 0; step >>= 1) {
        if (tid < step) {
            float av[TOPK], bv[TOPK]; int ai[TOPK], bi[TOPK];
            #pragma unroll
            for (int i = 0; i < TOPK; i++) {
                av[i] = ss[i * 256 + tid];        ai[i] = si[i * 256 + tid];
                bv[i] = ss[i * 256 + tid + step]; bi[i] = si[i * 256 + tid + step];
            }
            float mv[TOPK]; int mi[TOPK];
            int p = 0, q = 0;
            #pragma unroll
            for (int r = 0; r < TOPK; r++) {
                bool takeA = (av[p] > bv[q]) || (av[p] == bv[q] && ai[p] < bi[q]);
                if (takeA) { mv[r] = av[p]; mi[r] = ai[p]; p++; }
                else       { mv[r] = bv[q]; mi[r] = bi[q]; q++; }
            }
            #pragma unroll
            for (int i = 0; i < TOPK; i++) { ss[i * 256 + tid] = mv[i]; si[i * 256 + tid] = mi[i]; }
        }
        __syncthreads();
    }

    if (tid == 0) {
        float inv_t = 1.f / (fabsf(temp[0]) + 1e-8f);
        float sc[TOPK], e[TOPK], tot = 0.f;
        #pragma unroll
        for (int i = 0; i < TOPK; i++) sc[i] = ss[i * 256] * inv_t;
        float m = sc[0];
        #pragma unroll
        for (int i = 0; i < TOPK; i++) { e[i] = expf(sc[i] - m); tot += e[i]; }
        float r = 1.f / tot;
        #pragma unroll
        for (int i = 0; i < TOPK; i++) {
            out[b * TOPK + i] = (float)si[i * 256];              // top_idx (cast)
            out[BQ * TOPK + b * TOPK + i] = e[i] * r;            // probs
        }
    }
}

// ---------------- launcher ----------------
extern "C" void kernel_launch(void* const* d_in, const int* in_sizes, int n_in,
                              void* d_out, int out_size) {
    // Input order (metadata): query_embed, doc_embeds, [k], Wq, bq, ln_q_w, ln_q_b,
    //                         Wd, bd, ln_d_w, ln_d_b, W1, b1, W2, b2, temperature
    int off = (n_in >= 16) ? 1 : 0;   // whether scalar k appears at index 2
    const float* query = (const float*)d_in[0];
    const float* docs  = (const float*)d_in[1];
    const float* Wq    = (const float*)d_in[2 + off];
    const float* bq    = (const float*)d_in[3 + off];
    const float* lnqw  = (const float*)d_in[4 + off];
    const float* lnqb  = (const float*)d_in[5 + off];
    const float* Wd    = (const float*)d_in[6 + off];
    const float* bd    = (const float*)d_in[7 + off];
    const float* lndw  = (const float*)d_in[8 + off];
    const float* lndb  = (const float*)d_in[9 + off];
    const float* W1    = (const float*)d_in[10 + off];
    const float* b1    = (const float*)d_in[11 + off];
    const float* W2    = (const float*)d_in[12 + off];
    const float* b2    = (const float*)d_in[13 + off];
    const float* temp  = (const float*)d_in[14 + off];

    int N = in_sizes[1] / ZDIM;   // 20000

    float* dt_p; cudaGetSymbolAddress((void**)&dt_p, g_dt);
    float* da_p; cudaGetSymbolAddress((void**)&da_p, g_da);

    // 1. query path
    kq_kernel<<<BQ, 256>>>(query, Wq, bq, lnqw, lnqb, W1, b1);

    // 2. doc transform: d_t = LN(gelu(docs @ Wd + bd))
    int nblk = (N + 63) / 64;
    gemm_tile<ZDIM, true><<<nblk, 256>>>(docs, Wd, bd, lndw, lndb, dt_p, N);

    // 3. da = d_t @ W1[H:]
    gemm_tile<HDIM, false><<<nblk, 256>>>(dt_p, W1 + (size_t)HDIM * HDIM,
                                          nullptr, nullptr, nullptr, da_p, N);

    // 4. scores
    score_kernel<<<(N + 15) / 16, 256>>>(W2, b2, N);

    // 5. top-k + softmax -> output [idx(160), probs(160)] as float32
    topk_kernel<<<BQ, 256>>>(temp, (float*)d_out, N);
}

// round 3
// speedup vs baseline: 1.4002x; 1.4002x over previous
#include <cuda_runtime.h>
#include <math.h>
#include <stdint.h>

// Problem constants (fixed by dataset)
#define BQ    32        // batch (queries)
#define ZDIM  512       // input embed dim
#define HDIM  256       // hidden dim
#define NMAX  20032     // max docs rounded up to 64
#define TOPK  5

// ---------------- device scratch ----------------
__device__ __align__(16) float g_qa [BQ * HDIM];          // qa + b1
__device__ __align__(16) float g_dt [NMAX * HDIM];        // doc transform output
__device__ __align__(16) float g_da [NMAX * HDIM];        // d_t @ W1[H:]
__device__ __align__(16) float g_raw[BQ * NMAX];          // raw scores

// ---------------- helpers ----------------
// Fast Phi(x) = 0.5*(1+erf(x/sqrt(2))) via Abramowitz-Stegun 7.1.26.
// |erf err| <= 1.5e-7 absolute -> Phi err <= 7.5e-8. Branch-free.
__device__ __forceinline__ float fast_phi(float x) {
    float z = fabsf(x) * 0.70710678118f;
    float t = __fdividef(1.0f, fmaf(0.3275911f, z, 1.0f));   // rcp.approx + mul
    float poly = t * (0.254829592f +
               t * (-0.284496736f +
               t * (1.421413741f +
               t * (-1.453152027f +
               t * 1.061405429f))));
    float e = __expf(-z * z);                                 // ex2-based
    float erf_abs = fmaf(-poly, e, 1.0f);                     // erf(|z|)
    float erf_s = copysignf(erf_abs, x);
    return fmaf(0.5f, erf_s, 0.5f);
}

__device__ __forceinline__ float gelu_exact(float x) {
    return x * fast_phi(x);
}

__device__ __forceinline__ float warp_sum(float v) {
    #pragma unroll
    for (int o = 16; o > 0; o >>= 1) v += __shfl_xor_sync(0xffffffffu, v, o);
    return v;
}

// ---------------- query path: q_t = LN(gelu(q@Wq+bq)); qa = q_t@W1[:H] + b1 ----------------
__global__ void kq_kernel(const float* __restrict__ q,
                          const float* __restrict__ Wq, const float* __restrict__ bq,
                          const float* __restrict__ lnw, const float* __restrict__ lnb,
                          const float* __restrict__ W1, const float* __restrict__ b1) {
    __shared__ float sq[ZDIM];
    __shared__ float st[HDIM];
    __shared__ float red[16];
    int b = blockIdx.x, tid = threadIdx.x;
    sq[tid]       = q[b * ZDIM + tid];
    sq[tid + 256] = q[b * ZDIM + 256 + tid];
    __syncthreads();

    float acc = bq[tid];
    #pragma unroll 8
    for (int kk = 0; kk < ZDIM; kk++) acc = fmaf(sq[kk], Wq[kk * HDIM + tid], acc);
    float g = gelu_exact(acc);

    int lane = tid & 31, w = tid >> 5;
    float s = warp_sum(g);
    if (lane == 0) red[w] = s;
    __syncthreads();
    float tot = 0.f;
    #pragma unroll
    for (int i = 0; i < 8; i++) tot += red[i];
    float mean = tot * (1.f / HDIM);

    float d = g - mean;
    float v = warp_sum(d * d);
    if (lane == 0) red[8 + w] = v;
    __syncthreads();
    float vt = 0.f;
    #pragma unroll
    for (int i = 0; i < 8; i++) vt += red[8 + i];
    float inv = rsqrtf(vt * (1.f / HDIM) + 1e-5f);

    float y = d * inv * lnw[tid] + lnb[tid];
    st[tid] = y;
    __syncthreads();

    float acc2 = b1[tid];
    #pragma unroll 8
    for (int h = 0; h < HDIM; h++) acc2 = fmaf(st[h], W1[h * HDIM + tid], acc2);
    g_qa[b * HDIM + tid] = acc2;
}

// ---------------- tiled GEMM: out[M,256] = A[M,K] @ B[K,256] (+bias, gelu, LN optional) ----------------
template <int K, bool ACT>
__global__ __launch_bounds__(256, 2)
void gemm_tile(const float* __restrict__ A, const float* __restrict__ B,
               const float* __restrict__ bias,
               const float* __restrict__ lnw, const float* __restrict__ lnb,
               float* __restrict__ out, int M) {
    __shared__ float  sA[64][32];
    __shared__ float4 sB[32][64];
    int tid = threadIdx.x, lane = tid & 31, w = tid >> 5;
    int r0 = blockIdx.x * 64;

    float acc[8][8];
    #pragma unroll
    for (int i = 0; i < 8; i++)
        #pragma unroll
        for (int j = 0; j < 8; j++) acc[i][j] = 0.f;

    for (int kc = 0; kc < K; kc += 32) {
        #pragma unroll
        for (int t = 0; t < 2; t++) {           // 512 float4 of A-chunk
            int f = tid + 256 * t, r = f >> 3, kg = f & 7;
            float4 vv = make_float4(0.f, 0.f, 0.f, 0.f);
            if (r0 + r < M) vv = *(const float4*)&A[(size_t)(r0 + r) * K + kc + kg * 4];
            *(float4*)&sA[r][kg * 4] = vv;
        }
        #pragma unroll
        for (int t = 0; t < 8; t++) {           // 2048 float4 of B-chunk
            int f = tid + 256 * t, kk = f >> 6, cg = f & 63;
            sB[kk][cg] = *(const float4*)&B[(size_t)(kc + kk) * HDIM + cg * 4];
        }
        __syncthreads();
        #pragma unroll 8
        for (int kk = 0; kk < 32; kk++) {
            float a_[8];
            #pragma unroll
            for (int i = 0; i < 8; i++) a_[i] = sA[w * 8 + i][kk];   // warp-uniform broadcast
            float4 b0 = sB[kk][lane * 2], b1v = sB[kk][lane * 2 + 1];
            float b_[8] = {b0.x, b0.y, b0.z, b0.w, b1v.x, b1v.y, b1v.z, b1v.w};
            #pragma unroll
            for (int i = 0; i < 8; i++)
                #pragma unroll
                for (int j = 0; j < 8; j++) acc[i][j] = fmaf(a_[i], b_[j], acc[i][j]);
        }
        __syncthreads();
    }

    int c0 = lane * 8;
    if (ACT) {
        float bb[8], lw[8], lb[8];
        #pragma unroll
        for (int j = 0; j < 8; j++) { bb[j] = bias[c0 + j]; lw[j] = lnw[c0 + j]; lb[j] = lnb[c0 + j]; }
        #pragma unroll
        for (int i = 0; i < 8; i++) {
            float g[8];
            #pragma unroll
            for (int j = 0; j < 8; j++) g[j] = gelu_exact(acc[i][j] + bb[j]);
            float s = 0.f;
            #pragma unroll
            for (int j = 0; j < 8; j++) s += g[j];
            s = warp_sum(s);
            float mean = s * (1.f / HDIM);
            float v = 0.f;
            #pragma unroll
            for (int j = 0; j < 8; j++) { float d = g[j] - mean; v += d * d; }
            v = warp_sum(v);
            float inv = rsqrtf(v * (1.f / HDIM) + 1e-5f);
            int row = r0 + w * 8 + i;
            if (row < M) {
                float o[8];
                #pragma unroll
                for (int j = 0; j < 8; j++) o[j] = (g[j] - mean) * inv * lw[j] + lb[j];
                float4* op = (float4*)&out[(size_t)row * HDIM + c0];
                op[0] = make_float4(o[0], o[1], o[2], o[3]);
                op[1] = make_float4(o[4], o[5], o[6], o[7]);
            }
        }
    } else {
        #pragma unroll
        for (int i = 0; i < 8; i++) {
            int row = r0 + w * 8 + i;
            if (row < M) {
                float4* op = (float4*)&out[(size_t)row * HDIM + c0];
                op[0] = make_float4(acc[i][0], acc[i][1], acc[i][2], acc[i][3]);
                op[1] = make_float4(acc[i][4], acc[i][5], acc[i][6], acc[i][7]);
            }
        }
    }
}

// ---------------- score kernel: raw[b,n] = b2 + sum_h W2[h]*gelu(qa[b,h]+da[n,h]) ----------------
// Warp w handles b in {w, w+8, w+16, w+24}; lane owns h = lane*8 .. lane*8+7.
// qa rows live in registers for the whole n-loop (loaded once per block).
__global__ __launch_bounds__(256)
void score_kernel(const float* __restrict__ W2, const float* __restrict__ b2, int N) {
    int tid = threadIdx.x, lane = tid & 31, w = tid >> 5;

    float w2_[8];
    #pragma unroll
    for (int j = 0; j < 8; j++) w2_[j] = W2[lane * 8 + j];
    float b2v = b2[0];

    // Hoist qa[b][lane*8..+7] for the 4 b-values this warp owns.
    float qa_[4][8];
    #pragma unroll
    for (int bb = 0; bb < 4; bb++) {
        int b = w + bb * 8;
        const float4* qp = (const float4*)&g_qa[(size_t)b * HDIM + lane * 8];
        float4 q0 = qp[0], q1 = qp[1];
        qa_[bb][0] = q0.x; qa_[bb][1] = q0.y; qa_[bb][2] = q0.z; qa_[bb][3] = q0.w;
        qa_[bb][4] = q1.x; qa_[bb][5] = q1.y; qa_[bb][6] = q1.z; qa_[bb][7] = q1.w;
    }

    int n0 = blockIdx.x * 16;
    for (int t = 0; t < 16; t++) {
        int n = n0 + t;
        if (n >= N) break;
        const float4* dap = (const float4*)&g_da[(size_t)n * HDIM + lane * 8];
        float4 d0 = dap[0], d1 = dap[1];
        float da_[8] = {d0.x, d0.y, d0.z, d0.w, d1.x, d1.y, d1.z, d1.w};
        #pragma unroll
        for (int bb = 0; bb < 4; bb++) {
            int b = w + bb * 8;
            float acc = 0.f;
            #pragma unroll
            for (int j = 0; j < 8; j++) {
                float x = qa_[bb][j] + da_[j];
                acc = fmaf(w2_[j] * x, fast_phi(x), acc);   // w2*gelu(x)
            }
            acc = warp_sum(acc);
            if (lane == 0) g_raw[(size_t)b * N + n] = acc + b2v;
        }
    }
}

// ---------------- top-k (k=5, lowest-index tie break) + softmax ----------------
__global__ __launch_bounds__(256)
void topk_kernel(const float* __restrict__ temp, float* __restrict__ out, int N) {
    __shared__ float ss[TOPK * 256];
    __shared__ int   si[TOPK * 256];
    int b = blockIdx.x, tid = threadIdx.x;
    float s[TOPK]; int id[TOPK];
    #pragma unroll
    for (int i = 0; i < TOPK; i++) { s[i] = -__int_as_float(0x7f800000); id[i] = 0x7fffffff; }

    const float* row = &g_raw[(size_t)b * N];
    for (int n = tid; n < N; n += 256) {
        float v = row[n];
        if (v > s[TOPK - 1]) {
            int p = TOPK - 1;
            #pragma unroll
            for (int i = TOPK - 1; i > 0; i--) if (v > s[i - 1]) p = i - 1;
            #pragma unroll
            for (int i = TOPK - 1; i > 0; i--) if (i > p) { s[i] = s[i - 1]; id[i] = id[i - 1]; }
            s[p] = v; id[p] = n;
        }
    }
    #pragma unroll
    for (int i = 0; i < TOPK; i++) { ss[i * 256 + tid] = s[i]; si[i * 256 + tid] = id[i]; }
    __syncthreads();

    for (int step = 128; step > 0; step >>= 1) {
        if (tid < step) {
            float av[TOPK], bv[TOPK]; int ai[TOPK], bi[TOPK];
            #pragma unroll
            for (int i = 0; i < TOPK; i++) {
                av[i] = ss[i * 256 + tid];        ai[i] = si[i * 256 + tid];
                bv[i] = ss[i * 256 + tid + step]; bi[i] = si[i * 256 + tid + step];
            }
            float mv[TOPK]; int mi[TOPK];
            int p = 0, q = 0;
            #pragma unroll
            for (int r = 0; r < TOPK; r++) {
                bool takeA = (av[p] > bv[q]) || (av[p] == bv[q] && ai[p] < bi[q]);
                if (takeA) { mv[r] = av[p]; mi[r] = ai[p]; p++; }
                else       { mv[r] = bv[q]; mi[r] = bi[q]; q++; }
            }
            #pragma unroll
            for (int i = 0; i < TOPK; i++) { ss[i * 256 + tid] = mv[i]; si[i * 256 + tid] = mi[i]; }
        }
        __syncthreads();
    }

    if (tid == 0) {
        float inv_t = 1.f / (fabsf(temp[0]) + 1e-8f);
        float sc[TOPK], e[TOPK], tot = 0.f;
        #pragma unroll
        for (int i = 0; i < TOPK; i++) sc[i] = ss[i * 256] * inv_t;
        float m = sc[0];
        #pragma unroll
        for (int i = 0; i < TOPK; i++) { e[i] = expf(sc[i] - m); tot += e[i]; }
        float r = 1.f / tot;
        #pragma unroll
        for (int i = 0; i < TOPK; i++) {
            out[b * TOPK + i] = (float)si[i * 256];              // top_idx (cast)
            out[BQ * TOPK + b * TOPK + i] = e[i] * r;            // probs
        }
    }
}

// ---------------- launcher ----------------
extern "C" void kernel_launch(void* const* d_in, const int* in_sizes, int n_in,
                              void* d_out, int out_size) {
    int off = (n_in >= 16) ? 1 : 0;   // whether scalar k appears at index 2
    const float* query = (const float*)d_in[0];
    const float* docs  = (const float*)d_in[1];
    const float* Wq    = (const float*)d_in[2 + off];
    const float* bq    = (const float*)d_in[3 + off];
    const float* lnqw  = (const float*)d_in[4 + off];
    const float* lnqb  = (const float*)d_in[5 + off];
    const float* Wd    = (const float*)d_in[6 + off];
    const float* bd    = (const float*)d_in[7 + off];
    const float* lndw  = (const float*)d_in[8 + off];
    const float* lndb  = (const float*)d_in[9 + off];
    const float* W1    = (const float*)d_in[10 + off];
    const float* b1    = (const float*)d_in[11 + off];
    const float* W2    = (const float*)d_in[12 + off];
    const float* b2    = (const float*)d_in[13 + off];
    const float* temp  = (const float*)d_in[14 + off];

    int N = in_sizes[1] / ZDIM;   // 20000

    float* dt_p; cudaGetSymbolAddress((void**)&dt_p, g_dt);
    float* da_p; cudaGetSymbolAddress((void**)&da_p, g_da);

    // 1. query path
    kq_kernel<<<BQ, 256>>>(query, Wq, bq, lnqw, lnqb, W1, b1);

    // 2. doc transform: d_t = LN(gelu(docs @ Wd + bd))
    int nblk = (N + 63) / 64;
    gemm_tile<ZDIM, true><<<nblk, 256>>>(docs, Wd, bd, lndw, lndb, dt_p, N);

    // 3. da = d_t @ W1[H:]
    gemm_tile<HDIM, false><<<nblk, 256>>>(dt_p, W1 + (size_t)HDIM * HDIM,
                                          nullptr, nullptr, nullptr, da_p, N);

    // 4. scores
    score_kernel<<<(N + 15) / 16, 256>>>(W2, b2, N);

    // 5. top-k + softmax -> output [idx(160), probs(160)] as float32
    topk_kernel<<<BQ, 256>>>(temp, (float*)d_out, N);
}

// round 4
// speedup vs baseline: 1.4641x; 1.0456x over previous
#include <cuda_runtime.h>
#include <math.h>
#include <stdint.h>

// Problem constants (fixed by dataset)
#define BQ    32        // batch (queries)
#define ZDIM  512       // input embed dim
#define HDIM  256       // hidden dim
#define NMAX  20032     // max docs rounded up to 64
#define TOPK  5

typedef unsigned long long u64;

// ---------------- device scratch ----------------
__device__ __align__(16) float g_qa [BQ * HDIM];          // qa + b1
__device__ __align__(16) float g_dt [NMAX * HDIM];        // doc transform output
__device__ __align__(16) float g_da [NMAX * HDIM];        // d_t @ W1[H:]
__device__ __align__(16) float g_raw[BQ * NMAX];          // raw scores

// ---------------- packed f32x2 primitives (sm_100a) ----------------
__device__ __forceinline__ u64 pk2(float lo, float hi) {
    u64 r; asm("mov.b64 %0, {%1,%2};" : "=l"(r) : "f"(lo), "f"(hi)); return r;
}
__device__ __forceinline__ void upk2(u64 v, float& lo, float& hi) {
    asm("mov.b64 {%0,%1}, %2;" : "=f"(lo), "=f"(hi) : "l"(v));
}
__device__ __forceinline__ u64 fma2(u64 a, u64 b, u64 c) {
    u64 d; asm("fma.rn.f32x2 %0, %1, %2, %3;" : "=l"(d) : "l"(a), "l"(b), "l"(c)); return d;
}
__device__ __forceinline__ u64 mul2(u64 a, u64 b) {
    u64 d; asm("mul.rn.f32x2 %0, %1, %2;" : "=l"(d) : "l"(a), "l"(b)); return d;
}
__device__ __forceinline__ u64 add2(u64 a, u64 b) {
    u64 d; asm("add.rn.f32x2 %0, %1, %2;" : "=l"(d) : "l"(a), "l"(b)); return d;
}
__device__ __forceinline__ u64 and2(u64 a, u64 b) {
    u64 d; asm("and.b64 %0, %1, %2;" : "=l"(d) : "l"(a), "l"(b)); return d;
}
__device__ __forceinline__ u64 or2(u64 a, u64 b) {
    u64 d; asm("or.b64 %0, %1, %2;" : "=l"(d) : "l"(a), "l"(b)); return d;
}
__device__ __forceinline__ float rcp_ap(float x) {
    float r; asm("rcp.approx.f32 %0, %1;" : "=f"(r) : "f"(x)); return r;
}
__device__ __forceinline__ float ex2_ap(float x) {
    float r; asm("ex2.approx.f32 %0, %1;" : "=f"(r) : "f"(x)); return r;
}

// ---------------- scalar helpers ----------------
// Fast Phi(x) = 0.5*(1+erf(x/sqrt(2))) via Abramowitz-Stegun 7.1.26.
__device__ __forceinline__ float fast_phi(float x) {
    float z = fabsf(x) * 0.70710678118f;
    float t = __fdividef(1.0f, fmaf(0.3275911f, z, 1.0f));
    float poly = t * (0.254829592f +
               t * (-0.284496736f +
               t * (1.421413741f +
               t * (-1.453152027f +
               t * 1.061405429f))));
    float e = __expf(-z * z);
    float erf_abs = fmaf(-poly, e, 1.0f);
    float erf_s = copysignf(erf_abs, x);
    return fmaf(0.5f, erf_s, 0.5f);
}
__device__ __forceinline__ float gelu_exact(float x) { return x * fast_phi(x); }

__device__ __forceinline__ float warp_sum(float v) {
    #pragma unroll
    for (int o = 16; o > 0; o >>= 1) v += __shfl_xor_sync(0xffffffffu, v, o);
    return v;
}

// ---------------- query path ----------------
__global__ void kq_kernel(const float* __restrict__ q,
                          const float* __restrict__ Wq, const float* __restrict__ bq,
                          const float* __restrict__ lnw, const float* __restrict__ lnb,
                          const float* __restrict__ W1, const float* __restrict__ b1) {
    __shared__ float sq[ZDIM];
    __shared__ float st[HDIM];
    __shared__ float red[16];
    int b = blockIdx.x, tid = threadIdx.x;
    sq[tid]       = q[b * ZDIM + tid];
    sq[tid + 256] = q[b * ZDIM + 256 + tid];
    __syncthreads();

    float acc = bq[tid];
    #pragma unroll 8
    for (int kk = 0; kk < ZDIM; kk++) acc = fmaf(sq[kk], Wq[kk * HDIM + tid], acc);
    float g = gelu_exact(acc);

    int lane = tid & 31, w = tid >> 5;
    float s = warp_sum(g);
    if (lane == 0) red[w] = s;
    __syncthreads();
    float tot = 0.f;
    #pragma unroll
    for (int i = 0; i < 8; i++) tot += red[i];
    float mean = tot * (1.f / HDIM);

    float d = g - mean;
    float v = warp_sum(d * d);
    if (lane == 0) red[8 + w] = v;
    __syncthreads();
    float vt = 0.f;
    #pragma unroll
    for (int i = 0; i < 8; i++) vt += red[8 + i];
    float inv = rsqrtf(vt * (1.f / HDIM) + 1e-5f);

    float y = d * inv * lnw[tid] + lnb[tid];
    st[tid] = y;
    __syncthreads();

    float acc2 = b1[tid];
    #pragma unroll 8
    for (int h = 0; h < HDIM; h++) acc2 = fmaf(st[h], W1[h * HDIM + tid], acc2);
    g_qa[b * HDIM + tid] = acc2;
}

// ---------------- tiled GEMM (packed f32x2 mainloop) ----------------
template <int K, bool ACT>
__global__ __launch_bounds__(256, 2)
void gemm_tile(const float* __restrict__ A, const float* __restrict__ B,
               const float* __restrict__ bias,
               const float* __restrict__ lnw, const float* __restrict__ lnb,
               float* __restrict__ out, int M) {
    __shared__ float  sA[64][32];
    __shared__ float4 sB[32][64];
    int tid = threadIdx.x, lane = tid & 31, w = tid >> 5;
    int r0 = blockIdx.x * 64;

    u64 acc[8][4];                       // 8 rows x 4 column-pairs
    #pragma unroll
    for (int i = 0; i < 8; i++)
        #pragma unroll
        for (int j = 0; j < 4; j++) acc[i][j] = 0ull;

    for (int kc = 0; kc < K; kc += 32) {
        #pragma unroll
        for (int t = 0; t < 2; t++) {           // 512 float4 of A-chunk
            int f = tid + 256 * t, r = f >> 3, kg = f & 7;
            float4 vv = make_float4(0.f, 0.f, 0.f, 0.f);
            if (r0 + r < M) vv = *(const float4*)&A[(size_t)(r0 + r) * K + kc + kg * 4];
            *(float4*)&sA[r][kg * 4] = vv;
        }
        #pragma unroll
        for (int t = 0; t < 8; t++) {           // 2048 float4 of B-chunk
            int f = tid + 256 * t, kk = f >> 6, cg = f & 63;
            sB[kk][cg] = *(const float4*)&B[(size_t)(kc + kk) * HDIM + cg * 4];
        }
        __syncthreads();
        #pragma unroll 4
        for (int kk = 0; kk < 32; kk++) {
            u64 pa[8];
            #pragma unroll
            for (int i = 0; i < 8; i++) { float a = sA[w * 8 + i][kk]; pa[i] = pk2(a, a); }
            const ulonglong2* pbp = (const ulonglong2*)&sB[kk][lane * 2];
            ulonglong2 u0 = pbp[0], u1 = pbp[1];
            u64 pb[4] = {u0.x, u0.y, u1.x, u1.y};
            #pragma unroll
            for (int i = 0; i < 8; i++)
                #pragma unroll
                for (int j = 0; j < 4; j++) acc[i][j] = fma2(pa[i], pb[j], acc[i][j]);
        }
        __syncthreads();
    }

    int c0 = lane * 8;
    if (ACT) {
        float bb[8], lw[8], lb[8];
        #pragma unroll
        for (int j = 0; j < 8; j++) { bb[j] = bias[c0 + j]; lw[j] = lnw[c0 + j]; lb[j] = lnb[c0 + j]; }
        #pragma unroll
        for (int i = 0; i < 8; i++) {
            float f[8];
            #pragma unroll
            for (int j = 0; j < 4; j++) upk2(acc[i][j], f[2 * j], f[2 * j + 1]);
            float g[8];
            #pragma unroll
            for (int j = 0; j < 8; j++) g[j] = gelu_exact(f[j] + bb[j]);
            float s = 0.f;
            #pragma unroll
            for (int j = 0; j < 8; j++) s += g[j];
            s = warp_sum(s);
            float mean = s * (1.f / HDIM);
            float v = 0.f;
            #pragma unroll
            for (int j = 0; j < 8; j++) { float d = g[j] - mean; v += d * d; }
            v = warp_sum(v);
            float inv = rsqrtf(v * (1.f / HDIM) + 1e-5f);
            int row = r0 + w * 8 + i;
            if (row < M) {
                float o[8];
                #pragma unroll
                for (int j = 0; j < 8; j++) o[j] = (g[j] - mean) * inv * lw[j] + lb[j];
                float4* op = (float4*)&out[(size_t)row * HDIM + c0];
                op[0] = make_float4(o[0], o[1], o[2], o[3]);
                op[1] = make_float4(o[4], o[5], o[6], o[7]);
            }
        }
    } else {
        #pragma unroll
        for (int i = 0; i < 8; i++) {
            int row = r0 + w * 8 + i;
            if (row < M) {
                float f[8];
                #pragma unroll
                for (int j = 0; j < 4; j++) upk2(acc[i][j], f[2 * j], f[2 * j + 1]);
                float4* op = (float4*)&out[(size_t)row * HDIM + c0];
                op[0] = make_float4(f[0], f[1], f[2], f[3]);
                op[1] = make_float4(f[4], f[5], f[6], f[7]);
            }
        }
    }
}

// ---------------- score kernel (packed f32x2 gelu) ----------------
// raw[b,n] = b2 + sum_h W2[h]*gelu(qa[b,h]+da[n,h])
// Warp w handles b in {w, w+8, w+16, w+24}; lane owns h = lane*8 .. lane*8+7 (4 pairs).
__global__ __launch_bounds__(256)
void score_kernel(const float* __restrict__ W2, const float* __restrict__ b2, int N) {
    int tid = threadIdx.x, lane = tid & 31, w = tid >> 5;

    // packed constants
    const u64 cRS2  = pk2(0.70710678118f, 0.70710678118f);      // 1/sqrt(2)
    const u64 cP    = pk2(0.3275911f, 0.3275911f);
    const u64 cOne  = pk2(1.0f, 1.0f);
    const u64 cHalf = pk2(0.5f, 0.5f);
    const u64 cNL2E = pk2(-1.4426950408889634f, -1.4426950408889634f); // -log2(e)
    // negated A&S coefficients (Horner produces -poly)
    const u64 cN1 = pk2(-0.254829592f, -0.254829592f);
    const u64 cN2 = pk2( 0.284496736f,  0.284496736f);
    const u64 cN3 = pk2(-1.421413741f, -1.421413741f);
    const u64 cN4 = pk2( 1.453152027f,  1.453152027f);
    const u64 cN5 = pk2(-1.061405429f, -1.061405429f);
    const u64 mAbs  = 0x7fffffff7fffffffull;
    const u64 mSign = 0x8000000080000000ull;

    // packed W2 pairs for this lane
    u64 pw[4];
    {
        const ulonglong2* wp = (const ulonglong2*)&W2[lane * 8];
        ulonglong2 w0 = wp[0], w1 = wp[1];
        pw[0] = w0.x; pw[1] = w0.y; pw[2] = w1.x; pw[3] = w1.y;
    }
    float b2v = b2[0];

    // packed qa pairs for the 4 b's this warp owns
    u64 pq[4][4];
    #pragma unroll
    for (int bb = 0; bb < 4; bb++) {
        int b = w + bb * 8;
        const ulonglong2* qp = (const ulonglong2*)&g_qa[(size_t)b * HDIM + lane * 8];
        ulonglong2 q0 = qp[0], q1 = qp[1];
        pq[bb][0] = q0.x; pq[bb][1] = q0.y; pq[bb][2] = q1.x; pq[bb][3] = q1.y;
    }

    int n0 = blockIdx.x * 16;
    for (int t = 0; t < 16; t++) {
        int n = n0 + t;
        if (n >= N) break;
        u64 pd[4];
        {
            const ulonglong2* dp = (const ulonglong2*)&g_da[(size_t)n * HDIM + lane * 8];
            ulonglong2 d0 = dp[0], d1 = dp[1];
            pd[0] = d0.x; pd[1] = d0.y; pd[2] = d1.x; pd[3] = d1.y;
        }
        #pragma unroll
        for (int bb = 0; bb < 4; bb++) {
            int b = w + bb * 8;
            u64 pacc = 0ull;
            #pragma unroll
            for (int j = 0; j < 4; j++) {
                u64 px = add2(pq[bb][j], pd[j]);            // x = qa + da
                u64 pz = mul2(px, cRS2);                    // z = x/sqrt(2)
                u64 paz = and2(pz, mAbs);                   // |z|
                u64 pzz = mul2(pz, pz);                     // z^2
                u64 pwexp = mul2(pzz, cNL2E);               // -z^2*log2(e)
                u64 pden = fma2(cP, paz, cOne);             // 1 + p|z|
                float d0f, d1f; upk2(pden, d0f, d1f);
                u64 pt = pk2(rcp_ap(d0f), rcp_ap(d1f));     // t
                u64 pn = fma2(pt, cN5, cN4);
                pn = fma2(pt, pn, cN3);
                pn = fma2(pt, pn, cN2);
                pn = fma2(pt, pn, cN1);
                pn = mul2(pn, pt);                          // -poly
                float w0f, w1f; upk2(pwexp, w0f, w1f);
                u64 pe = pk2(ex2_ap(w0f), ex2_ap(w1f));     // e^{-z^2}
                u64 perf = fma2(pn, pe, cOne);              // 1 - poly*e = erf(|z|)
                u64 psgn = and2(px, mSign);
                perf = or2(perf, psgn);                     // copysign
                u64 pphi = fma2(perf, cHalf, cHalf);        // Phi(x)
                u64 pxw = mul2(px, pw[j]);                  // x*W2
                pacc = fma2(pxw, pphi, pacc);               // acc += x*W2*Phi
            }
            float a0, a1; upk2(pacc, a0, a1);
            float acc = warp_sum(a0 + a1);
            if (lane == 0) g_raw[(size_t)b * N + n] = acc + b2v;
        }
    }
}

// ---------------- top-k (k=5, lowest-index tie break) + softmax ----------------
__global__ __launch_bounds__(256)
void topk_kernel(const float* __restrict__ temp, float* __restrict__ out, int N) {
    __shared__ float ss[TOPK * 256];
    __shared__ int   si[TOPK * 256];
    int b = blockIdx.x, tid = threadIdx.x;
    float s[TOPK]; int id[TOPK];
    #pragma unroll
    for (int i = 0; i < TOPK; i++) { s[i] = -__int_as_float(0x7f800000); id[i] = 0x7fffffff; }

    const float* row = &g_raw[(size_t)b * N];
    for (int n = tid; n < N; n += 256) {
        float v = row[n];
        if (v > s[TOPK - 1]) {
            int p = TOPK - 1;
            #pragma unroll
            for (int i = TOPK - 1; i > 0; i--) if (v > s[i - 1]) p = i - 1;
            #pragma unroll
            for (int i = TOPK - 1; i > 0; i--) if (i > p) { s[i] = s[i - 1]; id[i] = id[i - 1]; }
            s[p] = v; id[p] = n;
        }
    }
    #pragma unroll
    for (int i = 0; i < TOPK; i++) { ss[i * 256 + tid] = s[i]; si[i * 256 + tid] = id[i]; }
    __syncthreads();

    for (int step = 128; step > 0; step >>= 1) {
        if (tid < step) {
            float av[TOPK], bv[TOPK]; int ai[TOPK], bi[TOPK];
            #pragma unroll
            for (int i = 0; i < TOPK; i++) {
                av[i] = ss[i * 256 + tid];        ai[i] = si[i * 256 + tid];
                bv[i] = ss[i * 256 + tid + step]; bi[i] = si[i * 256 + tid + step];
            }
            float mv[TOPK]; int mi[TOPK];
            int p = 0, q = 0;
            #pragma unroll
            for (int r = 0; r < TOPK; r++) {
                bool takeA = (av[p] > bv[q]) || (av[p] == bv[q] && ai[p] < bi[q]);
                if (takeA) { mv[r] = av[p]; mi[r] = ai[p]; p++; }
                else       { mv[r] = bv[q]; mi[r] = bi[q]; q++; }
            }
            #pragma unroll
            for (int i = 0; i < TOPK; i++) { ss[i * 256 + tid] = mv[i]; si[i * 256 + tid] = mi[i]; }
        }
        __syncthreads();
    }

    if (tid == 0) {
        float inv_t = 1.f / (fabsf(temp[0]) + 1e-8f);
        float sc[TOPK], e[TOPK], tot = 0.f;
        #pragma unroll
        for (int i = 0; i < TOPK; i++) sc[i] = ss[i * 256] * inv_t;
        float m = sc[0];
        #pragma unroll
        for (int i = 0; i < TOPK; i++) { e[i] = expf(sc[i] - m); tot += e[i]; }
        float r = 1.f / tot;
        #pragma unroll
        for (int i = 0; i < TOPK; i++) {
            out[b * TOPK + i] = (float)si[i * 256];              // top_idx (cast)
            out[BQ * TOPK + b * TOPK + i] = e[i] * r;            // probs
        }
    }
}

// ---------------- launcher ----------------
extern "C" void kernel_launch(void* const* d_in, const int* in_sizes, int n_in,
                              void* d_out, int out_size) {
    int off = (n_in >= 16) ? 1 : 0;   // whether scalar k appears at index 2
    const float* query = (const float*)d_in[0];
    const float* docs  = (const float*)d_in[1];
    const float* Wq    = (const float*)d_in[2 + off];
    const float* bq    = (const float*)d_in[3 + off];
    const float* lnqw  = (const float*)d_in[4 + off];
    const float* lnqb  = (const float*)d_in[5 + off];
    const float* Wd    = (const float*)d_in[6 + off];
    const float* bd    = (const float*)d_in[7 + off];
    const float* lndw  = (const float*)d_in[8 + off];
    const float* lndb  = (const float*)d_in[9 + off];
    const float* W1    = (const float*)d_in[10 + off];
    const float* b1    = (const float*)d_in[11 + off];
    const float* W2    = (const float*)d_in[12 + off];
    const float* b2    = (const float*)d_in[13 + off];
    const float* temp  = (const float*)d_in[14 + off];

    int N = in_sizes[1] / ZDIM;   // 20000

    float* dt_p; cudaGetSymbolAddress((void**)&dt_p, g_dt);
    float* da_p; cudaGetSymbolAddress((void**)&da_p, g_da);

    // 1. query path
    kq_kernel<<<BQ, 256>>>(query, Wq, bq, lnqw, lnqb, W1, b1);

    // 2. doc transform: d_t = LN(gelu(docs @ Wd + bd))
    int nblk = (N + 63) / 64;
    gemm_tile<ZDIM, true><<<nblk, 256>>>(docs, Wd, bd, lndw, lndb, dt_p, N);

    // 3. da = d_t @ W1[H:]
    gemm_tile<HDIM, false><<<nblk, 256>>>(dt_p, W1 + (size_t)HDIM * HDIM,
                                          nullptr, nullptr, nullptr, da_p, N);

    // 4. scores
    score_kernel<<<(N + 15) / 16, 256>>>(W2, b2, N);

    // 5. top-k + softmax -> output [idx(160), probs(160)] as float32
    topk_kernel<<<BQ, 256>>>(temp, (float*)d_out, N);
}

// round 8
// speedup vs baseline: 1.8394x; 1.2564x over previous
#include <cuda_runtime.h>
#include <cuda_bf16.h>
#include <math.h>
#include <stdint.h>

// Problem constants (fixed by dataset)
#define BQ    32
#define ZDIM  512
#define HDIM  256
#define NMAX  20032
#define TOPK  5

// ---------------- device scratch ----------------
__device__ __align__(16) float g_qa [BQ * HDIM];
__device__ __align__(16) float g_da [NMAX * HDIM];
__device__ __align__(16) float g_gel[NMAX * HDIM];            // gelu(docs@Wd+bd), pre-LN
__device__ __align__(16) float g_raw[BQ * NMAX];
__device__ __align__(16) __nv_bfloat16 g_dthi[NMAX * HDIM];
__device__ __align__(16) __nv_bfloat16 g_dtlo[NMAX * HDIM];
__device__ __align__(16) __nv_bfloat16 g_B1hi[HDIM * ZDIM];   // [n=256][k=512] = Wd^T hi
__device__ __align__(16) __nv_bfloat16 g_B1lo[HDIM * ZDIM];
__device__ __align__(16) __nv_bfloat16 g_B2hi[HDIM * HDIM];   // [n=256][k=256] = W1[H:]^T hi
__device__ __align__(16) __nv_bfloat16 g_B2lo[HDIM * HDIM];

// ---------------- PTX helpers (sm_80+ only; no 'a'-suffix features) ----------------
__device__ __forceinline__ uint32_t smem_to_u32(const void* p) {
    uint32_t a;
    asm("{ .reg .u64 t; cvta.to.shared.u64 t, %1; cvt.u32.u64 %0, t; }" : "=r"(a) : "l"(p));
    return a;
}

#define LDSM4(r, addr) \
    asm volatile("ldmatrix.sync.aligned.m8n8.x4.shared.b16 {%0,%1,%2,%3}, [%4];" \
        : "=r"((r)[0]), "=r"((r)[1]), "=r"((r)[2]), "=r"((r)[3]) : "r"(addr))

#define MMA16816(c, a, b) \
    asm volatile("mma.sync.aligned.m16n8k16.row.col.f32.bf16.bf16.f32 " \
        "{%0,%1,%2,%3}, {%4,%5,%6,%7}, {%8,%9}, {%0,%1,%2,%3};" \
        : "+f"((c)[0]), "+f"((c)[1]), "+f"((c)[2]), "+f"((c)[3]) \
        : "r"((a)[0]), "r"((a)[1]), "r"((a)[2]), "r"((a)[3]), \
          "r"((b)[0]), "r"((b)[1]))

// ---------------- math helpers ----------------
__device__ __forceinline__ float fast_phi(float x) {
    float z = fabsf(x) * 0.70710678118f;
    float t = __fdividef(1.0f, fmaf(0.3275911f, z, 1.0f));
    float poly = t * (0.254829592f +
               t * (-0.284496736f +
               t * (1.421413741f +
               t * (-1.453152027f +
               t * 1.061405429f))));
    float e = __expf(-z * z);
    float erf_abs = fmaf(-poly, e, 1.0f);
    float erf_s = copysignf(erf_abs, x);
    return fmaf(0.5f, erf_s, 0.5f);
}
__device__ __forceinline__ float gelu_exact(float x) { return x * fast_phi(x); }

__device__ __forceinline__ float warp_sum(float v) {
    #pragma unroll
    for (int o = 16; o > 0; o >>= 1) v += __shfl_xor_sync(0xffffffffu, v, o);
    return v;
}

__device__ __forceinline__ void split_bf16(float v, __nv_bfloat16& h, __nv_bfloat16& l) {
    h = __float2bfloat16_rn(v);
    l = __float2bfloat16_rn(v - __bfloat162float(h));
}

// ---------------- query path ----------------
__global__ void kq_kernel(const float* __restrict__ q,
                          const float* __restrict__ Wq, const float* __restrict__ bq,
                          const float* __restrict__ lnw, const float* __restrict__ lnb,
                          const float* __restrict__ W1, const float* __restrict__ b1) {
    __shared__ float sq[ZDIM];
    __shared__ float st[HDIM];
    __shared__ float red[16];
    int b = blockIdx.x, tid = threadIdx.x;
    sq[tid]       = q[b * ZDIM + tid];
    sq[tid + 256] = q[b * ZDIM + 256 + tid];
    __syncthreads();

    float acc = bq[tid];
    #pragma unroll 8
    for (int kk = 0; kk < ZDIM; kk++) acc = fmaf(sq[kk], Wq[kk * HDIM + tid], acc);
    float g = gelu_exact(acc);

    int lane = tid & 31, w = tid >> 5;
    float s = warp_sum(g);
    if (lane == 0) red[w] = s;
    __syncthreads();
    float tot = 0.f;
    #pragma unroll
    for (int i = 0; i < 8; i++) tot += red[i];
    float mean = tot * (1.f / HDIM);

    float d = g - mean;
    float v = warp_sum(d * d);
    if (lane == 0) red[8 + w] = v;
    __syncthreads();
    float vt = 0.f;
    #pragma unroll
    for (int i = 0; i < 8; i++) vt += red[8 + i];
    float inv = rsqrtf(vt * (1.f / HDIM) + 1e-5f);

    float y = d * inv * lnw[tid] + lnb[tid];
    st[tid] = y;
    __syncthreads();

    float acc2 = b1[tid];
    #pragma unroll 8
    for (int h = 0; h < HDIM; h++) acc2 = fmaf(st[h], W1[h * HDIM + tid], acc2);
    g_qa[b * HDIM + tid] = acc2;
}

// ---------------- B conversion: transpose + bf16 hi/lo split ----------------
__global__ void convert_B(const float* __restrict__ Wd, const float* __restrict__ W1h) {
    int idx = blockIdx.x * 256 + threadIdx.x;
    if (idx < HDIM * ZDIM) {
        int n = idx & (HDIM - 1), k = idx >> 8;
        float v = Wd[(size_t)k * HDIM + n];
        __nv_bfloat16 h, l; split_bf16(v, h, l);
        g_B1hi[(size_t)n * ZDIM + k] = h;
        g_B1lo[(size_t)n * ZDIM + k] = l;
    }
    int idx2 = idx - HDIM * ZDIM;
    if (idx2 >= 0 && idx2 < HDIM * HDIM) {
        int n = idx2 & (HDIM - 1), k = idx2 >> 8;
        float v = W1h[(size_t)k * HDIM + n];
        __nv_bfloat16 h, l; split_bf16(v, h, l);
        g_B2hi[(size_t)n * HDIM + k] = h;
        g_B2lo[(size_t)n * HDIM + k] = l;
    }
}

// ---------------- mma.sync GEMM: C[M,256] = A[M,K] @ B^T (B stored [256][K]) ----------------
// bf16 3-term split: C = Ah*Bh + Ah*Bl + Al*Bh, fp32 accumulators.
// Block: 128(M) x 128(N), 8 warps (4Mx2N), warp = 32x64. K chunk = 32, double-buffered.
#define PITCHB 80                   // bytes per smem row (32 bf16 data + 8 pad)
#define BUF_A_HI 0
#define BUF_A_LO 10240
#define BUF_B_HI 20480
#define BUF_B_LO 30720
#define BUF_STRIDE 40960
#define MMA_SMEM (2 * BUF_STRIDE)   // 81920 B

template <int KTOT, bool AF32, bool GELU_OUT>
__global__ __launch_bounds__(256)
void mma_gemm(const float* __restrict__ A32,
              const __nv_bfloat16* __restrict__ Ahi, const __nv_bfloat16* __restrict__ Alo,
              const __nv_bfloat16* __restrict__ Bhi, const __nv_bfloat16* __restrict__ Blo,
              const float* __restrict__ bias,
              float* __restrict__ outF, int M) {
    extern __shared__ char smem[];
    uint32_t sb = smem_to_u32(smem);
    const int tid = threadIdx.x, lane = tid & 31, w = tid >> 5;
    const int wm = w & 3, wn = w >> 2;
    const int m0 = blockIdx.x * 128, n0 = blockIdx.y * 128;
    constexpr int NC = KTOT / 32;

    float c[2][8][4];
    #pragma unroll
    for (int mi = 0; mi < 2; mi++)
        #pragma unroll
        for (int ni = 0; ni < 8; ni++)
            #pragma unroll
            for (int j = 0; j < 4; j++) c[mi][ni][j] = 0.f;

    // prefetch registers
    float4 a4[4];
    uint2 ah4[4], al4[4], bh4[4], bl4[4];

    auto gload = [&](int cc) {
        int kc = cc * 32;
        #pragma unroll
        for (int t = 0; t < 4; t++) {
            int f = t * 256 + tid, r = f >> 3, c4 = f & 7;
            int m = m0 + r;
            if constexpr (AF32) {
                a4[t] = (m < M) ? *(const float4*)&A32[(size_t)m * KTOT + kc + c4 * 4]
                                : make_float4(0.f, 0.f, 0.f, 0.f);
            } else {
                if (m < M) {
                    ah4[t] = *(const uint2*)&Ahi[(size_t)m * KTOT + kc + c4 * 4];
                    al4[t] = *(const uint2*)&Alo[(size_t)m * KTOT + kc + c4 * 4];
                } else { ah4[t] = make_uint2(0u, 0u); al4[t] = make_uint2(0u, 0u); }
            }
            bh4[t] = *(const uint2*)&Bhi[(size_t)(n0 + r) * KTOT + kc + c4 * 4];
            bl4[t] = *(const uint2*)&Blo[(size_t)(n0 + r) * KTOT + kc + c4 * 4];
        }
    };

    auto stsAll = [&](int s) {
        char* base = smem + s * BUF_STRIDE;
        #pragma unroll
        for (int t = 0; t < 4; t++) {
            int f = t * 256 + tid, r = f >> 3, c4 = f & 7;
            int off = r * PITCHB + c4 * 8;
            if constexpr (AF32) {
                __nv_bfloat162 h01, h23, l01, l23;
                split_bf16(a4[t].x, h01.x, l01.x); split_bf16(a4[t].y, h01.y, l01.y);
                split_bf16(a4[t].z, h23.x, l23.x); split_bf16(a4[t].w, h23.y, l23.y);
                *(__nv_bfloat162*)(base + BUF_A_HI + off)     = h01;
                *(__nv_bfloat162*)(base + BUF_A_HI + off + 4) = h23;
                *(__nv_bfloat162*)(base + BUF_A_LO + off)     = l01;
                *(__nv_bfloat162*)(base + BUF_A_LO + off + 4) = l23;
            } else {
                *(uint2*)(base + BUF_A_HI + off) = ah4[t];
                *(uint2*)(base + BUF_A_LO + off) = al4[t];
            }
            *(uint2*)(base + BUF_B_HI + off) = bh4[t];
            *(uint2*)(base + BUF_B_LO + off) = bl4[t];
        }
    };

    const int a_row = wm * 32 + (lane & 7) + ((lane >> 3) & 1) * 8;
    const int a_cb  = (lane >> 4) * 16;
    const int b_row = wn * 64 + (lane & 7) + ((lane >> 4) << 3);
    const int b_cb  = ((lane >> 3) & 1) * 16;

    auto mma_chunk = [&](int s) {
        uint32_t base = sb + s * BUF_STRIDE;
        #pragma unroll
        for (int ks = 0; ks < 2; ks++) {
            int kb = ks * 32;
            uint32_t ah[2][4], al[2][4], bh[4][4], bl[4][4];
            #pragma unroll
            for (int mi = 0; mi < 2; mi++) {
                uint32_t ad = base + BUF_A_HI + (a_row + mi * 16) * PITCHB + kb + a_cb;
                LDSM4(ah[mi], ad);
                LDSM4(al[mi], ad + (BUF_A_LO - BUF_A_HI));
            }
            #pragma unroll
            for (int bg = 0; bg < 4; bg++) {
                uint32_t bd = base + BUF_B_HI + (b_row + bg * 16) * PITCHB + kb + b_cb;
                LDSM4(bh[bg], bd);
                LDSM4(bl[bg], bd + (BUF_B_LO - BUF_B_HI));
            }
            #pragma unroll
            for (int mi = 0; mi < 2; mi++)
                #pragma unroll
                for (int ni = 0; ni < 8; ni++) {
                    uint32_t* bH = &bh[ni >> 1][(ni & 1) * 2];
                    uint32_t* bL = &bl[ni >> 1][(ni & 1) * 2];
                    MMA16816(c[mi][ni], ah[mi], bH);
                    MMA16816(c[mi][ni], ah[mi], bL);
                    MMA16816(c[mi][ni], al[mi], bH);
                }
        }
    };

    gload(0);
    stsAll(0);
    __syncthreads();
    for (int cc = 0; cc < NC; cc++) {
        if (cc + 1 < NC) gload(cc + 1);
        mma_chunk(cc & 1);
        if (cc + 1 < NC) stsAll((cc + 1) & 1);
        __syncthreads();
    }

    // epilogue
    #pragma unroll
    for (int mi = 0; mi < 2; mi++) {
        int r0 = m0 + wm * 32 + mi * 16 + (lane >> 2);
        #pragma unroll
        for (int ni = 0; ni < 8; ni++) {
            int col = n0 + wn * 64 + ni * 8 + (lane & 3) * 2;
            float* cf = c[mi][ni];
            if constexpr (GELU_OUT) {
                float b0 = bias[col], b1 = bias[col + 1];
                if (r0 < M) {
                    float2 o = make_float2(gelu_exact(cf[0] + b0), gelu_exact(cf[1] + b1));
                    *(float2*)&outF[(size_t)r0 * HDIM + col] = o;
                }
                if (r0 + 8 < M) {
                    float2 o = make_float2(gelu_exact(cf[2] + b0), gelu_exact(cf[3] + b1));
                    *(float2*)&outF[(size_t)(r0 + 8) * HDIM + col] = o;
                }
            } else {
                if (r0 < M)     *(float2*)&outF[(size_t)r0 * HDIM + col]       = make_float2(cf[0], cf[1]);
                if (r0 + 8 < M) *(float2*)&outF[(size_t)(r0 + 8) * HDIM + col] = make_float2(cf[2], cf[3]);
            }
        }
    }
}

// ---------------- LN over rows of g_gel -> bf16 hi/lo ----------------
__global__ __launch_bounds__(256)
void ln_split_kernel(const float* __restrict__ gin,
                     const float* __restrict__ lnw, const float* __restrict__ lnb,
                     __nv_bfloat16* __restrict__ hi, __nv_bfloat16* __restrict__ lo, int M) {
    int row = blockIdx.x * 8 + (threadIdx.x >> 5);
    int lane = threadIdx.x & 31;
    if (row >= M) return;
    const float4* p = (const float4*)&gin[(size_t)row * HDIM + lane * 8];
    float4 v0 = p[0], v1 = p[1];
    float vals[8] = {v0.x, v0.y, v0.z, v0.w, v1.x, v1.y, v1.z, v1.w};
    float s = 0.f, q = 0.f;
    #pragma unroll
    for (int j = 0; j < 8; j++) { s += vals[j]; q = fmaf(vals[j], vals[j], q); }
    s = warp_sum(s); q = warp_sum(q);
    float mean = s * (1.f / HDIM);
    float var  = q * (1.f / HDIM) - mean * mean;
    float inv  = rsqrtf(var + 1e-5f);
    __nv_bfloat162 h[4], l[4];
    #pragma unroll
    for (int j = 0; j < 8; j++) {
        int col = lane * 8 + j;
        float y = (vals[j] - mean) * inv * lnw[col] + lnb[col];
        __nv_bfloat16 hh, ll; split_bf16(y, hh, ll);
        ((__nv_bfloat16*)h)[j] = hh;
        ((__nv_bfloat16*)l)[j] = ll;
    }
    *(uint4*)&hi[(size_t)row * HDIM + lane * 8] = *(uint4*)h;
    *(uint4*)&lo[(size_t)row * HDIM + lane * 8] = *(uint4*)l;
}

// ---------------- score kernel (known-good) ----------------
__global__ __launch_bounds__(256)
void score_kernel(const float* __restrict__ W2, const float* __restrict__ b2, int N) {
    int tid = threadIdx.x, lane = tid & 31, w = tid >> 5;

    float w2_[8];
    #pragma unroll
    for (int j = 0; j < 8; j++) w2_[j] = W2[lane * 8 + j];
    float b2v = b2[0];

    float qa_[4][8];
    #pragma unroll
    for (int bb = 0; bb < 4; bb++) {
        int b = w + bb * 8;
        const float4* qp = (const float4*)&g_qa[(size_t)b * HDIM + lane * 8];
        float4 q0 = qp[0], q1 = qp[1];
        qa_[bb][0] = q0.x; qa_[bb][1] = q0.y; qa_[bb][2] = q0.z; qa_[bb][3] = q0.w;
        qa_[bb][4] = q1.x; qa_[bb][5] = q1.y; qa_[bb][6] = q1.z; qa_[bb][7] = q1.w;
    }

    int n0 = blockIdx.x * 16;
    for (int t = 0; t < 16; t++) {
        int n = n0 + t;
        if (n >= N) break;
        const float4* dap = (const float4*)&g_da[(size_t)n * HDIM + lane * 8];
        float4 d0 = dap[0], d1 = dap[1];
        float da_[8] = {d0.x, d0.y, d0.z, d0.w, d1.x, d1.y, d1.z, d1.w};
        #pragma unroll
        for (int bb = 0; bb < 4; bb++) {
            int b = w + bb * 8;
            float acc = 0.f;
            #pragma unroll
            for (int j = 0; j < 8; j++) {
                float x = qa_[bb][j] + da_[j];
                acc = fmaf(w2_[j] * x, fast_phi(x), acc);
            }
            acc = warp_sum(acc);
            if (lane == 0) g_raw[(size_t)b * N + n] = acc + b2v;
        }
    }
}

// ---------------- top-k + softmax ----------------
__global__ __launch_bounds__(256)
void topk_kernel(const float* __restrict__ temp, float* __restrict__ out, int N) {
    __shared__ float ss[TOPK * 256];
    __shared__ int   si[TOPK * 256];
    int b = blockIdx.x, tid = threadIdx.x;
    float s[TOPK]; int id[TOPK];
    #pragma unroll
    for (int i = 0; i < TOPK; i++) { s[i] = -__int_as_float(0x7f800000); id[i] = 0x7fffffff; }

    const float* row = &g_raw[(size_t)b * N];
    for (int n = tid; n < N; n += 256) {
        float v = row[n];
        if (v > s[TOPK - 1]) {
            int p = TOPK - 1;
            #pragma unroll
            for (int i = TOPK - 1; i > 0; i--) if (v > s[i - 1]) p = i - 1;
            #pragma unroll
            for (int i = TOPK - 1; i > 0; i--) if (i > p) { s[i] = s[i - 1]; id[i] = id[i - 1]; }
            s[p] = v; id[p] = n;
        }
    }
    #pragma unroll
    for (int i = 0; i < TOPK; i++) { ss[i * 256 + tid] = s[i]; si[i * 256 + tid] = id[i]; }
    __syncthreads();

    for (int step = 128; step > 0; step >>= 1) {
        if (tid < step) {
            float av[TOPK], bv[TOPK]; int ai[TOPK], bi[TOPK];
            #pragma unroll
            for (int i = 0; i < TOPK; i++) {
                av[i] = ss[i * 256 + tid];        ai[i] = si[i * 256 + tid];
                bv[i] = ss[i * 256 + tid + step]; bi[i] = si[i * 256 + tid + step];
            }
            float mv[TOPK]; int mi[TOPK];
            int p = 0, q = 0;
            #pragma unroll
            for (int rr = 0; rr < TOPK; rr++) {
                bool takeA = (av[p] > bv[q]) || (av[p] == bv[q] && ai[p] < bi[q]);
                if (takeA) { mv[rr] = av[p]; mi[rr] = ai[p]; p++; }
                else       { mv[rr] = bv[q]; mi[rr] = bi[q]; q++; }
            }
            #pragma unroll
            for (int i = 0; i < TOPK; i++) { ss[i * 256 + tid] = mv[i]; si[i * 256 + tid] = mi[i]; }
        }
        __syncthreads();
    }

    if (tid == 0) {
        float inv_t = 1.f / (fabsf(temp[0]) + 1e-8f);
        float sc[TOPK], e[TOPK], tot = 0.f;
        #pragma unroll
        for (int i = 0; i < TOPK; i++) sc[i] = ss[i * 256] * inv_t;
        float m = sc[0];
        #pragma unroll
        for (int i = 0; i < TOPK; i++) { e[i] = expf(sc[i] - m); tot += e[i]; }
        float rr = 1.f / tot;
        #pragma unroll
        for (int i = 0; i < TOPK; i++) {
            out[b * TOPK + i] = (float)si[i * 256];
            out[BQ * TOPK + b * TOPK + i] = e[i] * rr;
        }
    }
}

// ---------------- launcher ----------------
extern "C" void kernel_launch(void* const* d_in, const int* in_sizes, int n_in,
                              void* d_out, int out_size) {
    int off = (n_in >= 16) ? 1 : 0;
    const float* query = (const float*)d_in[0];
    const float* docs  = (const float*)d_in[1];
    const float* Wq    = (const float*)d_in[2 + off];
    const float* bq    = (const float*)d_in[3 + off];
    const float* lnqw  = (const float*)d_in[4 + off];
    const float* lnqb  = (const float*)d_in[5 + off];
    const float* Wd    = (const float*)d_in[6 + off];
    const float* bd    = (const float*)d_in[7 + off];
    const float* lndw  = (const float*)d_in[8 + off];
    const float* lndb  = (const float*)d_in[9 + off];
    const float* W1    = (const float*)d_in[10 + off];
    const float* b1    = (const float*)d_in[11 + off];
    const float* W2    = (const float*)d_in[12 + off];
    const float* b2    = (const float*)d_in[13 + off];
    const float* temp  = (const float*)d_in[14 + off];

    int N = in_sizes[1] / ZDIM;

    float *da_p, *gel_p;
    cudaGetSymbolAddress((void**)&da_p,  g_da);
    cudaGetSymbolAddress((void**)&gel_p, g_gel);
    __nv_bfloat16 *dthi_p, *dtlo_p, *b1hi_p, *b1lo_p, *b2hi_p, *b2lo_p;
    cudaGetSymbolAddress((void**)&dthi_p, g_dthi);
    cudaGetSymbolAddress((void**)&dtlo_p, g_dtlo);
    cudaGetSymbolAddress((void**)&b1hi_p, g_B1hi);
    cudaGetSymbolAddress((void**)&b1lo_p, g_B1lo);
    cudaGetSymbolAddress((void**)&b2hi_p, g_B2hi);
    cudaGetSymbolAddress((void**)&b2lo_p, g_B2lo);

    cudaFuncSetAttribute((const void*)mma_gemm<ZDIM, true, true>,
                         cudaFuncAttributeMaxDynamicSharedMemorySize, MMA_SMEM);
    cudaFuncSetAttribute((const void*)mma_gemm<HDIM, false, false>,
                         cudaFuncAttributeMaxDynamicSharedMemorySize, MMA_SMEM);

    // 1. query path
    kq_kernel<<<BQ, 256>>>(query, Wq, bq, lnqw, lnqb, W1, b1);

    // 2. B matrices -> transposed bf16 hi/lo
    convert_B<<<(HDIM * ZDIM + HDIM * HDIM) / 256, 256>>>(Wd, W1 + (size_t)HDIM * HDIM);

    dim3 gg((N + 127) / 128, 2);
    // 3. gelu(docs @ Wd + bd) -> f32 (pre-LN)
    mma_gemm<ZDIM, true, true><<<gg, 256, MMA_SMEM>>>(
        docs, nullptr, nullptr, b1hi_p, b1lo_p, bd, gel_p, N);

    // 4. LN + bf16 hi/lo split -> d_t
    ln_split_kernel<<<(N + 7) / 8, 256>>>(gel_p, lndw, lndb, dthi_p, dtlo_p, N);

    // 5. da = d_t @ W1[H:] -> f32
    mma_gemm<HDIM, false, false><<<gg, 256, MMA_SMEM>>>(
        nullptr, dthi_p, dtlo_p, b2hi_p, b2lo_p, nullptr, da_p, N);

    // 6. scores
    score_kernel<<<(N + 15) / 16, 256>>>(W2, b2, N);

    // 7. top-k + softmax
    topk_kernel<<<BQ, 256>>>(temp, (float*)d_out, N);
}

// round 9
// speedup vs baseline: 1.9259x; 1.0470x over previous
#include <cuda_runtime.h>
#include <cuda_bf16.h>
#include <math.h>
#include <stdint.h>

// Problem constants (fixed by dataset)
#define BQ    32
#define ZDIM  512
#define HDIM  256
#define NMAX  20032
#define TOPK  5

// ---------------- device scratch ----------------
__device__ __align__(16) float g_qa [BQ * HDIM];
__device__ __align__(16) float g_da [NMAX * HDIM];
__device__ __align__(16) float g_raw[BQ * NMAX];
__device__ __align__(16) __nv_bfloat16 g_dthi[NMAX * HDIM];
__device__ __align__(16) __nv_bfloat16 g_dtlo[NMAX * HDIM];
__device__ __align__(16) __nv_bfloat16 g_B1hi[HDIM * ZDIM];   // [n=256][k=512] = Wd^T hi
__device__ __align__(16) __nv_bfloat16 g_B1lo[HDIM * ZDIM];
__device__ __align__(16) __nv_bfloat16 g_B2hi[HDIM * HDIM];   // [n=256][k=256] = W1[H:]^T hi
__device__ __align__(16) __nv_bfloat16 g_B2lo[HDIM * HDIM];

// ---------------- PTX helpers (sm_80+ only) ----------------
__device__ __forceinline__ uint32_t smem_to_u32(const void* p) {
    uint32_t a;
    asm("{ .reg .u64 t; cvta.to.shared.u64 t, %1; cvt.u32.u64 %0, t; }" : "=r"(a) : "l"(p));
    return a;
}

#define LDSM4(r, addr) \
    asm volatile("ldmatrix.sync.aligned.m8n8.x4.shared.b16 {%0,%1,%2,%3}, [%4];" \
        : "=r"((r)[0]), "=r"((r)[1]), "=r"((r)[2]), "=r"((r)[3]) : "r"(addr))

#define MMA16816(c, a, b) \
    asm volatile("mma.sync.aligned.m16n8k16.row.col.f32.bf16.bf16.f32 " \
        "{%0,%1,%2,%3}, {%4,%5,%6,%7}, {%8,%9}, {%0,%1,%2,%3};" \
        : "+f"((c)[0]), "+f"((c)[1]), "+f"((c)[2]), "+f"((c)[3]) \
        : "r"((a)[0]), "r"((a)[1]), "r"((a)[2]), "r"((a)[3]), \
          "r"((b)[0]), "r"((b)[1]))

// ---------------- math helpers ----------------
__device__ __forceinline__ float fast_phi(float x) {
    float z = fabsf(x) * 0.70710678118f;
    float t = __fdividef(1.0f, fmaf(0.3275911f, z, 1.0f));
    float poly = t * (0.254829592f +
               t * (-0.284496736f +
               t * (1.421413741f +
               t * (-1.453152027f +
               t * 1.061405429f))));
    float e = __expf(-z * z);
    float erf_abs = fmaf(-poly, e, 1.0f);
    float erf_s = copysignf(erf_abs, x);
    return fmaf(0.5f, erf_s, 0.5f);
}
__device__ __forceinline__ float gelu_exact(float x) { return x * fast_phi(x); }

__device__ __forceinline__ float warp_sum(float v) {
    #pragma unroll
    for (int o = 16; o > 0; o >>= 1) v += __shfl_xor_sync(0xffffffffu, v, o);
    return v;
}

__device__ __forceinline__ void split_bf16(float v, __nv_bfloat16& h, __nv_bfloat16& l) {
    h = __float2bfloat16_rn(v);
    l = __float2bfloat16_rn(v - __bfloat162float(h));
}

// ---------------- query path ----------------
__global__ void kq_kernel(const float* __restrict__ q,
                          const float* __restrict__ Wq, const float* __restrict__ bq,
                          const float* __restrict__ lnw, const float* __restrict__ lnb,
                          const float* __restrict__ W1, const float* __restrict__ b1) {
    __shared__ float sq[ZDIM];
    __shared__ float st[HDIM];
    __shared__ float red[16];
    int b = blockIdx.x, tid = threadIdx.x;
    sq[tid]       = q[b * ZDIM + tid];
    sq[tid + 256] = q[b * ZDIM + 256 + tid];
    __syncthreads();

    float acc = bq[tid];
    #pragma unroll 8
    for (int kk = 0; kk < ZDIM; kk++) acc = fmaf(sq[kk], Wq[kk * HDIM + tid], acc);
    float g = gelu_exact(acc);

    int lane = tid & 31, w = tid >> 5;
    float s = warp_sum(g);
    if (lane == 0) red[w] = s;
    __syncthreads();
    float tot = 0.f;
    #pragma unroll
    for (int i = 0; i < 8; i++) tot += red[i];
    float mean = tot * (1.f / HDIM);

    float d = g - mean;
    float v = warp_sum(d * d);
    if (lane == 0) red[8 + w] = v;
    __syncthreads();
    float vt = 0.f;
    #pragma unroll
    for (int i = 0; i < 8; i++) vt += red[8 + i];
    float inv = rsqrtf(vt * (1.f / HDIM) + 1e-5f);

    float y = d * inv * lnw[tid] + lnb[tid];
    st[tid] = y;
    __syncthreads();

    float acc2 = b1[tid];
    #pragma unroll 8
    for (int h = 0; h < HDIM; h++) acc2 = fmaf(st[h], W1[h * HDIM + tid], acc2);
    g_qa[b * HDIM + tid] = acc2;
}

// ---------------- B conversion: transpose + bf16 hi/lo split ----------------
__global__ void convert_B(const float* __restrict__ Wd, const float* __restrict__ W1h) {
    int idx = blockIdx.x * 256 + threadIdx.x;
    if (idx < HDIM * ZDIM) {
        int n = idx & (HDIM - 1), k = idx >> 8;
        float v = Wd[(size_t)k * HDIM + n];
        __nv_bfloat16 h, l; split_bf16(v, h, l);
        g_B1hi[(size_t)n * ZDIM + k] = h;
        g_B1lo[(size_t)n * ZDIM + k] = l;
    }
    int idx2 = idx - HDIM * ZDIM;
    if (idx2 >= 0 && idx2 < HDIM * HDIM) {
        int n = idx2 & (HDIM - 1), k = idx2 >> 8;
        float v = W1h[(size_t)k * HDIM + n];
        __nv_bfloat16 h, l; split_bf16(v, h, l);
        g_B2hi[(size_t)n * HDIM + k] = h;
        g_B2lo[(size_t)n * HDIM + k] = l;
    }
}

// ---------------- mma.sync GEMM: C[64-tile M, 256 N] = A @ B^T  (B stored [256][K]) ----------------
// bf16 3-term split: C = Ah*Bh + Ah*Bl + Al*Bh, fp32 accumulators.
// Block: 64(M) x 256(N), 8 warps (2Mx4N), warp = 32x64. K chunk = 32, double-buffered.
// LN_OUT: fused bias+gelu+LayerNorm+bf16split epilogue (writes outHi/outLo).
#define PITCHB 80
#define BUF_A_HI 0
#define BUF_A_LO 5120
#define BUF_B_HI 10240
#define BUF_B_LO 30720
#define BUF_STRIDE 51200
#define MMA_SMEM (2 * BUF_STRIDE)   // 102400 B

template <int KTOT, bool AF32, bool LN_OUT>
__global__ __launch_bounds__(256)
void mma_gemm(const float* __restrict__ A32,
              const __nv_bfloat16* __restrict__ Ahi, const __nv_bfloat16* __restrict__ Alo,
              const __nv_bfloat16* __restrict__ Bhi, const __nv_bfloat16* __restrict__ Blo,
              const float* __restrict__ bias,
              const float* __restrict__ lnw, const float* __restrict__ lnb,
              float* __restrict__ outF,
              __nv_bfloat16* __restrict__ outHi, __nv_bfloat16* __restrict__ outLo,
              int M) {
    extern __shared__ char smem[];
    uint32_t sb = smem_to_u32(smem);
    const int tid = threadIdx.x, lane = tid & 31, w = tid >> 5;
    const int wm = w & 1, wn = w >> 1;
    const int m0 = blockIdx.x * 64;
    constexpr int NC = KTOT / 32;

    float c[2][8][4];
    #pragma unroll
    for (int mi = 0; mi < 2; mi++)
        #pragma unroll
        for (int ni = 0; ni < 8; ni++)
            #pragma unroll
            for (int j = 0; j < 4; j++) c[mi][ni][j] = 0.f;

    // prefetch registers
    float4 a4[2];
    uint4 ahv, alv;
    uint4 bh4[4], bl4[4];

    auto gload = [&](int cc) {
        int kc = cc * 32;
        if constexpr (AF32) {
            #pragma unroll
            for (int t = 0; t < 2; t++) {           // 512 float4 (64 rows x 32 f32)
                int f = t * 256 + tid, r = f >> 3, c4 = f & 7;
                int m = m0 + r;
                a4[t] = (m < M) ? *(const float4*)&A32[(size_t)m * KTOT + kc + c4 * 4]
                                : make_float4(0.f, 0.f, 0.f, 0.f);
            }
        } else {
            int r = tid >> 2, cg = tid & 3;         // 256 uint4 (64 rows x 32 bf16)
            int m = m0 + r;
            if (m < M) {
                ahv = *(const uint4*)&Ahi[(size_t)m * KTOT + kc + cg * 8];
                alv = *(const uint4*)&Alo[(size_t)m * KTOT + kc + cg * 8];
            } else { ahv = make_uint4(0,0,0,0); alv = make_uint4(0,0,0,0); }
        }
        #pragma unroll
        for (int t = 0; t < 4; t++) {               // 1024 uint4 (256 rows x 32 bf16)
            int f = t * 256 + tid, r = f >> 2, cg = f & 3;
            bh4[t] = *(const uint4*)&Bhi[(size_t)r * KTOT + kc + cg * 8];
            bl4[t] = *(const uint4*)&Blo[(size_t)r * KTOT + kc + cg * 8];
        }
    };

    auto stsAll = [&](int s) {
        char* base = smem + s * BUF_STRIDE;
        if constexpr (AF32) {
            #pragma unroll
            for (int t = 0; t < 2; t++) {
                int f = t * 256 + tid, r = f >> 3, c4 = f & 7;
                int off = r * PITCHB + c4 * 8;
                __nv_bfloat162 h01, h23, l01, l23;
                split_bf16(a4[t].x, h01.x, l01.x); split_bf16(a4[t].y, h01.y, l01.y);
                split_bf16(a4[t].z, h23.x, l23.x); split_bf16(a4[t].w, h23.y, l23.y);
                *(__nv_bfloat162*)(base + BUF_A_HI + off)     = h01;
                *(__nv_bfloat162*)(base + BUF_A_HI + off + 4) = h23;
                *(__nv_bfloat162*)(base + BUF_A_LO + off)     = l01;
                *(__nv_bfloat162*)(base + BUF_A_LO + off + 4) = l23;
            }
        } else {
            int r = tid >> 2, cg = tid & 3;
            int off = r * PITCHB + cg * 16;
            *(uint4*)(base + BUF_A_HI + off) = ahv;
            *(uint4*)(base + BUF_A_LO + off) = alv;
        }
        #pragma unroll
        for (int t = 0; t < 4; t++) {
            int f = t * 256 + tid, r = f >> 2, cg = f & 3;
            int off = r * PITCHB + cg * 16;
            *(uint4*)(base + BUF_B_HI + off) = bh4[t];
            *(uint4*)(base + BUF_B_LO + off) = bl4[t];
        }
    };

    const int a_row = wm * 32 + (lane & 7) + ((lane >> 3) & 1) * 8;
    const int a_cb  = (lane >> 4) * 16;
    const int b_row = wn * 64 + (lane & 7) + ((lane >> 4) << 3);
    const int b_cb  = ((lane >> 3) & 1) * 16;

    auto mma_chunk = [&](int s) {
        uint32_t base = sb + s * BUF_STRIDE;
        #pragma unroll
        for (int ks = 0; ks < 2; ks++) {
            int kb = ks * 32;
            uint32_t ah[2][4], al[2][4], bh[4][4], bl[4][4];
            #pragma unroll
            for (int mi = 0; mi < 2; mi++) {
                uint32_t ad = base + BUF_A_HI + (a_row + mi * 16) * PITCHB + kb + a_cb;
                LDSM4(ah[mi], ad);
                LDSM4(al[mi], ad + (BUF_A_LO - BUF_A_HI));
            }
            #pragma unroll
            for (int bg = 0; bg < 4; bg++) {
                uint32_t bd = base + BUF_B_HI + (b_row + bg * 16) * PITCHB + kb + b_cb;
                LDSM4(bh[bg], bd);
                LDSM4(bl[bg], bd + (BUF_B_LO - BUF_B_HI));
            }
            #pragma unroll
            for (int mi = 0; mi < 2; mi++)
                #pragma unroll
                for (int ni = 0; ni < 8; ni++) {
                    uint32_t* bH = &bh[ni >> 1][(ni & 1) * 2];
                    uint32_t* bL = &bl[ni >> 1][(ni & 1) * 2];
                    MMA16816(c[mi][ni], ah[mi], bH);
                    MMA16816(c[mi][ni], ah[mi], bL);
                    MMA16816(c[mi][ni], al[mi], bH);
                }
        }
    };

    gload(0);
    stsAll(0);
    __syncthreads();
    for (int cc = 0; cc < NC; cc++) {
        if (cc + 1 < NC) gload(cc + 1);
        mma_chunk(cc & 1);
        if (cc + 1 < NC) stsAll((cc + 1) & 1);
        __syncthreads();
    }

    // ---------------- epilogue ----------------
    // Thread owns rows: wm*32 + mi*16 + (lane>>2) + jr*8  (mi,jr in {0,1})
    // and cols: wn*64 + ni*8 + (lane&3)*2 + {0,1}
    if constexpr (LN_OUT) {
        float sums[2][2] = {{0.f, 0.f}, {0.f, 0.f}};
        float sqs [2][2] = {{0.f, 0.f}, {0.f, 0.f}};
        #pragma unroll
        for (int mi = 0; mi < 2; mi++)
            #pragma unroll
            for (int ni = 0; ni < 8; ni++) {
                int cb = wn * 64 + ni * 8 + (lane & 3) * 2;
                float b0 = bias[cb], b1 = bias[cb + 1];
                float g0 = gelu_exact(c[mi][ni][0] + b0);
                float g1 = gelu_exact(c[mi][ni][1] + b1);
                float g2 = gelu_exact(c[mi][ni][2] + b0);
                float g3 = gelu_exact(c[mi][ni][3] + b1);
                c[mi][ni][0] = g0; c[mi][ni][1] = g1; c[mi][ni][2] = g2; c[mi][ni][3] = g3;
                sums[mi][0] += g0 + g1; sums[mi][1] += g2 + g3;
                sqs [mi][0] += g0 * g0 + g1 * g1;
                sqs [mi][1] += g2 * g2 + g3 * g3;
            }
        // reduce over the 4-lane group (same rows)
        #pragma unroll
        for (int d = 1; d <= 2; d <<= 1) {
            #pragma unroll
            for (int mi = 0; mi < 2; mi++)
                #pragma unroll
                for (int jr = 0; jr < 2; jr++) {
                    sums[mi][jr] += __shfl_xor_sync(0xffffffffu, sums[mi][jr], d);
                    sqs [mi][jr] += __shfl_xor_sync(0xffffffffu, sqs [mi][jr], d);
                }
        }
        float* red = (float*)smem;   // 64 rows x 8 floats (sum[4], sq[4]) = 2KB; smem free now
        if ((lane & 3) == 0) {
            #pragma unroll
            for (int mi = 0; mi < 2; mi++)
                #pragma unroll
                for (int jr = 0; jr < 2; jr++) {
                    int rl = wm * 32 + mi * 16 + (lane >> 2) + jr * 8;
                    red[rl * 8 + wn]     = sums[mi][jr];
                    red[rl * 8 + 4 + wn] = sqs[mi][jr];
                }
        }
        __syncthreads();
        float mean_[2][2], inv_[2][2];
        #pragma unroll
        for (int mi = 0; mi < 2; mi++)
            #pragma unroll
            for (int jr = 0; jr < 2; jr++) {
                int rl = wm * 32 + mi * 16 + (lane >> 2) + jr * 8;
                float s = red[rl * 8] + red[rl * 8 + 1] + red[rl * 8 + 2] + red[rl * 8 + 3];
                float q = red[rl * 8 + 4] + red[rl * 8 + 5] + red[rl * 8 + 6] + red[rl * 8 + 7];
                float mean = s * (1.f / HDIM);
                float var  = q * (1.f / HDIM) - mean * mean;
                mean_[mi][jr] = mean;
                inv_[mi][jr]  = rsqrtf(var + 1e-5f);
            }
        #pragma unroll
        for (int mi = 0; mi < 2; mi++)
            #pragma unroll
            for (int ni = 0; ni < 8; ni++) {
                int cb = wn * 64 + ni * 8 + (lane & 3) * 2;
                float lw0 = lnw[cb], lw1 = lnw[cb + 1];
                float lb0 = lnb[cb], lb1 = lnb[cb + 1];
                #pragma unroll
                for (int jr = 0; jr < 2; jr++) {
                    int rl = wm * 32 + mi * 16 + (lane >> 2) + jr * 8;
                    int m2 = m0 + rl;
                    if (m2 < M) {
                        float y0 = (c[mi][ni][jr * 2]     - mean_[mi][jr]) * inv_[mi][jr] * lw0 + lb0;
                        float y1 = (c[mi][ni][jr * 2 + 1] - mean_[mi][jr]) * inv_[mi][jr] * lw1 + lb1;
                        __nv_bfloat162 h, l;
                        split_bf16(y0, h.x, l.x);
                        split_bf16(y1, h.y, l.y);
                        *(__nv_bfloat162*)&outHi[(size_t)m2 * HDIM + cb] = h;
                        *(__nv_bfloat162*)&outLo[(size_t)m2 * HDIM + cb] = l;
                    }
                }
            }
    } else {
        #pragma unroll
        for (int mi = 0; mi < 2; mi++) {
            int r0 = m0 + wm * 32 + mi * 16 + (lane >> 2);
            #pragma unroll
            for (int ni = 0; ni < 8; ni++) {
                int col = wn * 64 + ni * 8 + (lane & 3) * 2;
                float* cf = c[mi][ni];
                if (r0 < M)     *(float2*)&outF[(size_t)r0 * HDIM + col]       = make_float2(cf[0], cf[1]);
                if (r0 + 8 < M) *(float2*)&outF[(size_t)(r0 + 8) * HDIM + col] = make_float2(cf[2], cf[3]);
            }
        }
    }
}

// ---------------- score kernel: 2 b's per warp, grid.y = b-half ----------------
__global__ __launch_bounds__(256)
void score_kernel(const float* __restrict__ W2, const float* __restrict__ b2, int N) {
    int tid = threadIdx.x, lane = tid & 31, w = tid >> 5;
    int b_base = blockIdx.y * 16 + w;

    float w2_[8];
    #pragma unroll
    for (int j = 0; j < 8; j++) w2_[j] = W2[lane * 8 + j];
    float b2v = b2[0];

    float qa_[2][8];
    #pragma unroll
    for (int bb = 0; bb < 2; bb++) {
        int b = b_base + bb * 8;
        const float4* qp = (const float4*)&g_qa[(size_t)b * HDIM + lane * 8];
        float4 q0 = qp[0], q1 = qp[1];
        qa_[bb][0] = q0.x; qa_[bb][1] = q0.y; qa_[bb][2] = q0.z; qa_[bb][3] = q0.w;
        qa_[bb][4] = q1.x; qa_[bb][5] = q1.y; qa_[bb][6] = q1.z; qa_[bb][7] = q1.w;
    }

    int n0 = blockIdx.x * 16;
    for (int t = 0; t < 16; t++) {
        int n = n0 + t;
        if (n >= N) break;
        const float4* dap = (const float4*)&g_da[(size_t)n * HDIM + lane * 8];
        float4 d0 = dap[0], d1 = dap[1];
        float da_[8] = {d0.x, d0.y, d0.z, d0.w, d1.x, d1.y, d1.z, d1.w};
        #pragma unroll
        for (int bb = 0; bb < 2; bb++) {
            int b = b_base + bb * 8;
            float acc = 0.f;
            #pragma unroll
            for (int j = 0; j < 8; j++) {
                float x = qa_[bb][j] + da_[j];
                acc = fmaf(w2_[j] * x, fast_phi(x), acc);
            }
            acc = warp_sum(acc);
            if (lane == 0) g_raw[(size_t)b * N + n] = acc + b2v;
        }
    }
}

// ---------------- top-k + softmax ----------------
__global__ __launch_bounds__(256)
void topk_kernel(const float* __restrict__ temp, float* __restrict__ out, int N) {
    __shared__ float ss[TOPK * 256];
    __shared__ int   si[TOPK * 256];
    int b = blockIdx.x, tid = threadIdx.x;
    float s[TOPK]; int id[TOPK];
    #pragma unroll
    for (int i = 0; i < TOPK; i++) { s[i] = -__int_as_float(0x7f800000); id[i] = 0x7fffffff; }

    const float* row = &g_raw[(size_t)b * N];
    for (int n = tid; n < N; n += 256) {
        float v = row[n];
        if (v > s[TOPK - 1]) {
            int p = TOPK - 1;
            #pragma unroll
            for (int i = TOPK - 1; i > 0; i--) if (v > s[i - 1]) p = i - 1;
            #pragma unroll
            for (int i = TOPK - 1; i > 0; i--) if (i > p) { s[i] = s[i - 1]; id[i] = id[i - 1]; }
            s[p] = v; id[p] = n;
        }
    }
    #pragma unroll
    for (int i = 0; i < TOPK; i++) { ss[i * 256 + tid] = s[i]; si[i * 256 + tid] = id[i]; }
    __syncthreads();

    for (int step = 128; step > 0; step >>= 1) {
        if (tid < step) {
            float av[TOPK], bv[TOPK]; int ai[TOPK], bi[TOPK];
            #pragma unroll
            for (int i = 0; i < TOPK; i++) {
                av[i] = ss[i * 256 + tid];        ai[i] = si[i * 256 + tid];
                bv[i] = ss[i * 256 + tid + step]; bi[i] = si[i * 256 + tid + step];
            }
            float mv[TOPK]; int mi[TOPK];
            int p = 0, q = 0;
            #pragma unroll
            for (int rr = 0; rr < TOPK; rr++) {
                bool takeA = (av[p] > bv[q]) || (av[p] == bv[q] && ai[p] < bi[q]);
                if (takeA) { mv[rr] = av[p]; mi[rr] = ai[p]; p++; }
                else       { mv[rr] = bv[q]; mi[rr] = bi[q]; q++; }
            }
            #pragma unroll
            for (int i = 0; i < TOPK; i++) { ss[i * 256 + tid] = mv[i]; si[i * 256 + tid] = mi[i]; }
        }
        __syncthreads();
    }

    if (tid == 0) {
        float inv_t = 1.f / (fabsf(temp[0]) + 1e-8f);
        float sc[TOPK], e[TOPK], tot = 0.f;
        #pragma unroll
        for (int i = 0; i < TOPK; i++) sc[i] = ss[i * 256] * inv_t;
        float m = sc[0];
        #pragma unroll
        for (int i = 0; i < TOPK; i++) { e[i] = expf(sc[i] - m); tot += e[i]; }
        float rr = 1.f / tot;
        #pragma unroll
        for (int i = 0; i < TOPK; i++) {
            out[b * TOPK + i] = (float)si[i * 256];
            out[BQ * TOPK + b * TOPK + i] = e[i] * rr;
        }
    }
}

// ---------------- launcher ----------------
extern "C" void kernel_launch(void* const* d_in, const int* in_sizes, int n_in,
                              void* d_out, int out_size) {
    int off = (n_in >= 16) ? 1 : 0;
    const float* query = (const float*)d_in[0];
    const float* docs  = (const float*)d_in[1];
    const float* Wq    = (const float*)d_in[2 + off];
    const float* bq    = (const float*)d_in[3 + off];
    const float* lnqw  = (const float*)d_in[4 + off];
    const float* lnqb  = (const float*)d_in[5 + off];
    const float* Wd    = (const float*)d_in[6 + off];
    const float* bd    = (const float*)d_in[7 + off];
    const float* lndw  = (const float*)d_in[8 + off];
    const float* lndb  = (const float*)d_in[9 + off];
    const float* W1    = (const float*)d_in[10 + off];
    const float* b1    = (const float*)d_in[11 + off];
    const float* W2    = (const float*)d_in[12 + off];
    const float* b2    = (const float*)d_in[13 + off];
    const float* temp  = (const float*)d_in[14 + off];

    int N = in_sizes[1] / ZDIM;

    float* da_p;
    cudaGetSymbolAddress((void**)&da_p, g_da);
    __nv_bfloat16 *dthi_p, *dtlo_p, *b1hi_p, *b1lo_p, *b2hi_p, *b2lo_p;
    cudaGetSymbolAddress((void**)&dthi_p, g_dthi);
    cudaGetSymbolAddress((void**)&dtlo_p, g_dtlo);
    cudaGetSymbolAddress((void**)&b1hi_p, g_B1hi);
    cudaGetSymbolAddress((void**)&b1lo_p, g_B1lo);
    cudaGetSymbolAddress((void**)&b2hi_p, g_B2hi);
    cudaGetSymbolAddress((void**)&b2lo_p, g_B2lo);

    cudaFuncSetAttribute((const void*)mma_gemm<ZDIM, true, true>,
                         cudaFuncAttributeMaxDynamicSharedMemorySize, MMA_SMEM);
    cudaFuncSetAttribute((const void*)mma_gemm<HDIM, false, false>,
                         cudaFuncAttributeMaxDynamicSharedMemorySize, MMA_SMEM);

    // 1. query path
    kq_kernel<<<BQ, 256>>>(query, Wq, bq, lnqw, lnqb, W1, b1);

    // 2. B matrices -> transposed bf16 hi/lo
    convert_B<<<(HDIM * ZDIM + HDIM * HDIM) / 256, 256>>>(Wd, W1 + (size_t)HDIM * HDIM);

    int nblk = (N + 63) / 64;
    // 3. d_t = LN(gelu(docs @ Wd + bd)) -> bf16 hi/lo (fused epilogue)
    mma_gemm<ZDIM, true, true><<<nblk, 256, MMA_SMEM>>>(
        docs, nullptr, nullptr, b1hi_p, b1lo_p, bd, lndw, lndb,
        nullptr, dthi_p, dtlo_p, N);

    // 4. da = d_t @ W1[H:] -> f32
    mma_gemm<HDIM, false, false><<<nblk, 256, MMA_SMEM>>>(
        nullptr, dthi_p, dtlo_p, b2hi_p, b2lo_p, nullptr, nullptr, nullptr,
        da_p, nullptr, nullptr, N);

    // 5. scores (b split across grid.y)
    dim3 sg((N + 15) / 16, 2);
    score_kernel<<<sg, 256>>>(W2, b2, N);

    // 6. top-k + softmax
    topk_kernel<<<BQ, 256>>>(temp, (float*)d_out, N);
}